// round 17
// baseline (speedup 1.0000x reference)
#include <cuda_runtime.h>
#include <math.h>

// Problem dims
#define BB 64
#define SS 1024
#define EE 256
#define HH 1024
#define GG 4096   // 4*H
#define PP 256    // projection size
#define NCTA 128  // persistent grid, 1 CTA/SM (smem-bound), all co-resident

typedef unsigned long long u64;

// ---------------- device scratch (no cudaMalloc allowed) ----------------
__device__ float g_xT[SS * BB * EE];          // x transposed to [t][b][e]
__device__ float g_WihT[2][EE * GG];          // W_ih^T  [e][g]
__device__ float g_WhhT[2][EE * GG];          // W_hh^T  [e][g]
__device__ float g_WhrT[2][HH * PP];          // W_hr^T  [u][p]
__device__ float g_bias[2][GG];               // b_ih + b_hh
__device__ float g_xg_f[268435456];           // xg fwd [t][ublk][gate][u15][b]
__device__ float g_xg_b[268435456];           // xg bwd same layout
__device__ float g_hT[2][PP * BB];            // projected hidden, [dir][p][b]
__device__ float g_hpT[2][HH * BB];           // o*tanh(c), [dir][u][b]
// per-direction two-level tree barrier (max 16 concurrent atomics per address)
__device__ unsigned g_leaf[2][4];             // 4 leaf counters of 16 CTAs each
__device__ unsigned g_root[2];                // root counter (4 leaf-leaders)
__device__ unsigned g_epoch[2];               // per-dir monotonic epoch

// ---------------- f32x2 packed-FMA helpers (Blackwell FFMA2) ----------------
__device__ __forceinline__ u64 pack2(float x, float y) {
    u64 r; asm("mov.b64 %0, {%1, %2};" : "=l"(r) : "f"(x), "f"(y)); return r;
}
__device__ __forceinline__ void unpack2(u64 v, float& x, float& y) {
    asm("mov.b64 {%0, %1}, %2;" : "=f"(x), "=f"(y) : "l"(v));
}
__device__ __forceinline__ u64 ffma2(u64 a, u64 b, u64 c) {
    u64 d; asm("fma.rn.f32x2 %0, %1, %2, %3;" : "=l"(d) : "l"(a), "l"(b), "l"(c)); return d;
}

// ---------------- activation helpers ----------------
__device__ __forceinline__ float sigf(float x) {
    return 1.0f / (1.0f + __expf(-x));
}
__device__ __forceinline__ float tanh_acc(float x) {
    float ax = fabsf(x);
    float e  = __expf(-2.0f * ax);
    float r  = (1.0f - e) / (1.0f + e);
    return x < 0.0f ? -r : r;
}

// Per-direction grid barrier over 64 CTAs, two-level tree to avoid the
// single-address L2 atomic serialization (cyc = n_conc*32*0.854): leaf groups
// of 16 -> root of 4 -> epoch. All 64 CTAs of a dir are co-resident (128 CTAs
// < 148 SMs), so spinning is deadlock-free. Release/acquire via __threadfence.
__device__ __forceinline__ void gsync_dir(int d, int grp, unsigned target) {
    __syncthreads();
    if (threadIdx.x == 0) {
        __threadfence();                       // release my CTA's writes
        unsigned o = atomicAdd(&g_leaf[d][grp], 1);
        bool done = false;
        if (o == 15) {                         // last of my 16-CTA leaf group
            unsigned r = atomicAdd(&g_root[d], 1);
            if (r == 3) {                      // last leaf group of this dir
                g_leaf[d][0] = 0; g_leaf[d][1] = 0;
                g_leaf[d][2] = 0; g_leaf[d][3] = 0;
                g_root[d] = 0;
                __threadfence();               // resets visible before release
                atomicAdd(&g_epoch[d], 1);
                done = true;
            }
        }
        if (!done) {
            while ((int)(*(volatile unsigned*)&g_epoch[d] - target) < 0) { }
        }
        __threadfence();                       // acquire peers' writes
    }
    __syncthreads();
}

// ---------------- prep: transposes, bias fuse, state zero ----------------
__global__ void prep_kernel(
    const float* __restrict__ x,
    const float* __restrict__ WihF, const float* __restrict__ WhhF,
    const float* __restrict__ bihF, const float* __restrict__ bhhF,
    const float* __restrict__ WhrF,
    const float* __restrict__ WihB, const float* __restrict__ WhhB,
    const float* __restrict__ bihB, const float* __restrict__ bhhB,
    const float* __restrict__ WhrB)
{
    size_t tid = (size_t)blockIdx.x * blockDim.x + threadIdx.x;
    size_t stride = (size_t)gridDim.x * blockDim.x;

    // xT[t][b][e] = x[b][t][e]
    for (size_t o = tid; o < (size_t)SS * BB * EE; o += stride) {
        unsigned e = (unsigned)(o & (EE - 1));
        unsigned b = (unsigned)((o >> 8) & (BB - 1));
        unsigned t = (unsigned)(o >> 14);
        g_xT[o] = x[((size_t)b * SS + t) * EE + e];
    }
    // W_ihT / W_hhT : [e][g] = W[g][e]
    for (size_t o = tid; o < (size_t)2 * EE * GG; o += stride) {
        unsigned d = (unsigned)(o >> 20);
        unsigned r = (unsigned)(o & (EE * GG - 1));
        unsigned g = r & (GG - 1);
        unsigned e = r >> 12;
        const float* Wih = d ? WihB : WihF;
        const float* Whh = d ? WhhB : WhhF;
        g_WihT[d][r] = Wih[(size_t)g * EE + e];
        g_WhhT[d][r] = Whh[(size_t)g * EE + e];
    }
    // W_hrT[u][p] = W_hr[p][u]
    for (size_t o = tid; o < (size_t)2 * HH * PP; o += stride) {
        unsigned d = (unsigned)(o >> 18);
        unsigned r = (unsigned)(o & (HH * PP - 1));
        unsigned p = r & (PP - 1);
        unsigned u = r >> 8;
        const float* Whr = d ? WhrB : WhrF;
        g_WhrT[d][r] = Whr[(size_t)p * HH + u];
    }
    // bias = b_ih + b_hh
    for (size_t o = tid; o < (size_t)2 * GG; o += stride) {
        unsigned d = (unsigned)(o >> 12);
        unsigned g = (unsigned)(o & (GG - 1));
        g_bias[d][g] = d ? (bihB[g] + bhhB[g]) : (bihF[g] + bhhF[g]);
    }
    // zero h (every replay must restart from h=0; c is smem-resident, zeroed in-kernel)
    for (size_t o = tid; o < (size_t)2 * PP * BB; o += stride) ((float*)g_hT)[o] = 0.0f;
}

// ---------------- xg = xT @ W_ihT + bias  (M=65536, K=256, N=4096, z=dir) ----
// Tile 64x64 (one tile == one t), BK=16, 256 threads, 4x4 micro, FFMA2.
// Epilogue restages through smem to emit the recurrence-friendly layout
//   xg[t][u>>4][gate][u&15][b]  with coalesced 256B row stores.
__global__ __launch_bounds__(256) void xg_gemm_kernel() {
    __shared__ float As[16 * 68];   // [k][m], padded
    __shared__ float Bs[16 * 68];   // [k][n], padded
    __shared__ float sT[64 * 68];   // [n][m] staging, padded
    const int d = blockIdx.z;
    const float* __restrict__ Wt = g_WihT[d];
    float* __restrict__ outp = d ? g_xg_b : g_xg_f;
    const unsigned m0 = blockIdx.x * 64;       // tile covers one t (m = t*64 + b)
    const unsigned n0 = blockIdx.y * 64;       // within one gate (1024 % 64 == 0)
    const int tid = threadIdx.x;
    const int tn = tid & 15, tm = tid >> 4;
    const int lm = tid >> 2, lk4 = (tid & 3) * 4;       // A loader
    const int lbk = tid >> 4, lbn4 = (tid & 15) * 4;    // B loader

    u64 acc[4][2] = {};   // [mi][n-pair]

    for (int kk = 0; kk < EE; kk += 16) {
        float4 av = *(const float4*)&g_xT[(size_t)(m0 + lm) * EE + kk + lk4];
        float4 bv = *(const float4*)&Wt[(size_t)(kk + lbk) * GG + n0 + lbn4];
        __syncthreads();
        As[(lk4 + 0) * 68 + lm] = av.x;
        As[(lk4 + 1) * 68 + lm] = av.y;
        As[(lk4 + 2) * 68 + lm] = av.z;
        As[(lk4 + 3) * 68 + lm] = av.w;
        Bs[lbk * 68 + lbn4 + 0] = bv.x;
        Bs[lbk * 68 + lbn4 + 1] = bv.y;
        Bs[lbk * 68 + lbn4 + 2] = bv.z;
        Bs[lbk * 68 + lbn4 + 3] = bv.w;
        __syncthreads();
#pragma unroll
        for (int k = 0; k < 16; k++) {
            float4 a = *(const float4*)&As[k * 68 + tm * 4];
            float4 b = *(const float4*)&Bs[k * 68 + tn * 4];
            u64 b01 = pack2(b.x, b.y), b23 = pack2(b.z, b.w);
            u64 a0 = pack2(a.x, a.x), a1 = pack2(a.y, a.y);
            u64 a2 = pack2(a.z, a.z), a3 = pack2(a.w, a.w);
            acc[0][0] = ffma2(a0, b01, acc[0][0]); acc[0][1] = ffma2(a0, b23, acc[0][1]);
            acc[1][0] = ffma2(a1, b01, acc[1][0]); acc[1][1] = ffma2(a1, b23, acc[1][1]);
            acc[2][0] = ffma2(a2, b01, acc[2][0]); acc[2][1] = ffma2(a2, b23, acc[2][1]);
            acc[3][0] = ffma2(a3, b01, acc[3][0]); acc[3][1] = ffma2(a3, b23, acc[3][1]);
        }
    }
    // stage [n][m] then write new layout with coalesced rows
#pragma unroll
    for (int mi = 0; mi < 4; mi++) {
        float4 v;
        unpack2(acc[mi][0], v.x, v.y);
        unpack2(acc[mi][1], v.z, v.w);
        sT[(tn * 4 + 0) * 68 + tm * 4 + mi] = v.x;
        sT[(tn * 4 + 1) * 68 + tm * 4 + mi] = v.y;
        sT[(tn * 4 + 2) * 68 + tm * 4 + mi] = v.z;
        sT[(tn * 4 + 3) * 68 + tm * 4 + mi] = v.w;
    }
    __syncthreads();
    const int gate = n0 >> 10;
    const int ub   = n0 & 1023;
    float* op = outp + (size_t)m0 * 4096;   // = t * 262144
#pragma unroll
    for (int q = 0; q < 4; q++) {
        int idx4 = tid + q * 256;
        int nl = idx4 >> 4;
        int m4 = (idx4 & 15) * 4;
        int u  = ub + nl;
        float bz = g_bias[d][n0 + nl];
        float4 v = *(const float4*)&sT[nl * 68 + m4];
        v.x += bz; v.y += bz; v.z += bz; v.w += bz;
        *(float4*)&op[(size_t)(u >> 4) * 4096 + gate * 1024 + (u & 15) * 64 + m4] = v;
    }
}

// ---------------- persistent recurrence, SMEM-resident weights ----------------
// 128 CTAs x 256 thr, 212.5 KB dynamic smem, 1 CTA/SM.
// Phase A: CTA=(dir, u-block 16): gates 64b x (4 gates x 16 u), K=256; Whh slice
//          (64 KB) and cell state c (4 KB) SMEM-resident.
// Phase B: CTA=(dir, b-block 16, p-block 16): h = hp @ Whr^T, K=1024 split x4;
//          Whr slice (64 KB) SMEM-resident.
// xg prefetch for step t+1 is software-pipelined into phase B of step t.
// Barriers are per-direction (all data deps are dir-local), two-level tree.
#define SM_WHH 0                          // 16384 floats
#define SM_WHR 16384                      // 16384
#define SM_H   32768                      // 16384 (phase-A h tile / phase-B hp tile)
#define SM_PRE 49152                      // 64*65 = 4160 (preacts / reduce buf)
#define SM_C   53312                      // 64*17 = 1088 (cell state, padded)
#define SM_TOTF 54400                     // total floats -> 217600 bytes

__global__ __launch_bounds__(256) void lstm_recur2(float* __restrict__ out) {
    extern __shared__ float smem[];
    float* sWhh = smem + SM_WHH;
    float* sWhr = smem + SM_WHR;
    float* sH   = smem + SM_H;
    float* sPre = smem + SM_PRE;
    float* sC   = smem + SM_C;

    const int tid = threadIdx.x;
    const int cta = blockIdx.x;
    const int d   = cta >> 6;
    const int r6  = cta & 63;
    const int grp = r6 >> 4;              // barrier leaf group (16 CTAs)
    const int u0  = r6 * 16;              // phase A u-block
    const int bB0 = (r6 >> 4) * 16;       // phase B batch block
    const int p0  = (r6 & 15) * 16;       // phase B p block

    const float* __restrict__ xg   = d ? g_xg_b : g_xg_f;
    const float* __restrict__ WhhT = g_WhhT[d];
    const float* __restrict__ WhrT = g_WhrT[d];
    float* __restrict__ hT  = g_hT[d];
    float* __restrict__ hpT = g_hpT[d];

    // ---- one-time resident fills ----
#pragma unroll
    for (int q = 0; q < 16; q++) {        // sWhh[k*64 + gate*16 + ul]
        int idx4 = tid + q * 256;
        int k  = idx4 >> 4;
        int n4 = (idx4 & 15) * 4;
        int gate = n4 >> 4;
        int ul = n4 & 15;
        *(float4*)&sWhh[k * 64 + n4] =
            *(const float4*)&WhhT[(size_t)k * GG + gate * HH + u0 + ul];
    }
#pragma unroll
    for (int q = 0; q < 16; q++) {        // sWhr[u*16 + pl]
        int idx4 = tid + q * 256;
        int u = idx4 >> 2;
        int pl4 = (idx4 & 3) * 4;
        *(float4*)&sWhr[u * 16 + pl4] = *(const float4*)&WhrT[(size_t)u * PP + p0 + pl4];
    }
    for (int i = tid; i < 64 * 17; i += 256) sC[i] = 0.0f;
    __syncthreads();

    // phase-A compute map: warp w: m-half (w&1)*32, n-quarter (w>>1)*16
    const int w = tid >> 5, l = tid & 31;
    const int am = (w & 1) * 32 + (l >> 2) * 4;   // 4-m base
    const int bn = (w >> 1) * 16 + (l & 3) * 4;   // 4-n base
    // cell map: (u = tid>>4, b = (tid&15)*4 + j)
    const int cu  = tid >> 4;
    const int cb4 = (tid & 15) * 4;
    // phase-B map
    const int ks = tid >> 6;              // K split 0..3
    const int rr = tid & 63;
    const int bl = rr & 15, pq = rr >> 4;

    unsigned tgt = 0;
    // Safe: this dir's epoch can't advance until all 64 of its CTAs reach
    // their first gsync_dir, which happens only after this read.
    if (tid == 0) tgt = *(volatile unsigned*)&g_epoch[d];

    // ---- peeled xg prefetch for t=0 (pipelined thereafter) ----
    float4 xq0, xq1, xq2, xq3;
    {
        const int tp0 = d ? (SS - 1) : 0;
        const float* xb = xg + (size_t)tp0 * 262144 + (size_t)r6 * 4096;
        xq0 = *(const float4*)&xb[0 * 1024 + tid * 4];
        xq1 = *(const float4*)&xb[1 * 1024 + tid * 4];
        xq2 = *(const float4*)&xb[2 * 1024 + tid * 4];
        xq3 = *(const float4*)&xb[3 * 1024 + tid * 4];
    }

    for (int t = 0; t < SS; t++) {
        const int tpos = d ? (SS - 1 - t) : t;

        // ---------- Phase A ----------
        // h tile: contiguous 64 KB copy hT -> sH ([k][64 b])
#pragma unroll
        for (int q = 0; q < 16; q++) {
            int idx4 = tid + q * 256;
            *(float4*)&sH[idx4 * 4] = *(const float4*)&hT[idx4 * 4];
        }
        __syncthreads();

        // gate GEMM: 64b x 64n, K=256, all operands in SMEM, no syncs
        u64 acc[4][2] = {};
#pragma unroll 8
        for (int k = 0; k < 256; k++) {
            float4 a = *(const float4*)&sH[k * 64 + am];
            ulonglong2 b = *(const ulonglong2*)&sWhh[k * 64 + bn];
            u64 a0 = pack2(a.x, a.x), a1 = pack2(a.y, a.y);
            u64 a2 = pack2(a.z, a.z), a3 = pack2(a.w, a.w);
            acc[0][0] = ffma2(a0, b.x, acc[0][0]); acc[0][1] = ffma2(a0, b.y, acc[0][1]);
            acc[1][0] = ffma2(a1, b.x, acc[1][0]); acc[1][1] = ffma2(a1, b.y, acc[1][1]);
            acc[2][0] = ffma2(a2, b.x, acc[2][0]); acc[2][1] = ffma2(a2, b.y, acc[2][1]);
            acc[3][0] = ffma2(a3, b.x, acc[3][0]); acc[3][1] = ffma2(a3, b.y, acc[3][1]);
        }
        // stage preacts sPre[b*65 + n]  (n = gate*16 + ul)
#pragma unroll
        for (int mi = 0; mi < 4; mi++) {
            float4 v;
            unpack2(acc[mi][0], v.x, v.y);
            unpack2(acc[mi][1], v.z, v.w);
            sPre[(am + mi) * 65 + bn + 0] = v.x;
            sPre[(am + mi) * 65 + bn + 1] = v.y;
            sPre[(am + mi) * 65 + bn + 2] = v.z;
            sPre[(am + mi) * 65 + bn + 3] = v.w;
        }
        __syncthreads();

        // cell update: 4 b-contiguous cells per thread, c SMEM-resident
        {
            float hout[4];
            const float* xi  = (const float*)&xq0;
            const float* xf  = (const float*)&xq1;
            const float* xgv = (const float*)&xq2;
            const float* xo  = (const float*)&xq3;
#pragma unroll
            for (int j = 0; j < 4; j++) {
                int b = cb4 + j;
                float p_i = sPre[b * 65 +      cu] + xi[j];
                float p_f = sPre[b * 65 + 16 + cu] + xf[j];
                float p_g = sPre[b * 65 + 32 + cu] + xgv[j];
                float p_o = sPre[b * 65 + 48 + cu] + xo[j];
                float iv = sigf(p_i), fv = sigf(p_f);
                float gv = tanh_acc(p_g), ov = sigf(p_o);
                float cv = fv * sC[b * 17 + cu] + iv * gv;
                sC[b * 17 + cu] = cv;
                hout[j] = ov * tanh_acc(cv);
            }
            *(float4*)&hpT[(size_t)(u0 + cu) * 64 + cb4] = *(float4*)hout;
        }
        gsync_dir(d, grp, ++tgt);

        // ---------- Phase B: h = hp @ Whr^T ----------
        // hp tile: sH[u*16 + b] from hpT[u*64 + bB0 + b]
#pragma unroll
        for (int q = 0; q < 16; q++) {
            int idx4 = tid + q * 256;
            int u = idx4 >> 2;
            int b4 = (idx4 & 3) * 4;
            *(float4*)&sH[u * 16 + b4] = *(const float4*)&hpT[(size_t)u * 64 + bB0 + b4];
        }
        __syncthreads();

        // pipelined xg prefetch for step t+1 (xg is read-only; independent of
        // all barriers — issued here so the 256-iter FFMA loop + trailing
        // barrier hide the DRAM latency)
        if (t + 1 < SS) {
            const int tnext = d ? (SS - 2 - t) : (t + 1);
            const float* xb = xg + (size_t)tnext * 262144 + (size_t)r6 * 4096;
            xq0 = *(const float4*)&xb[0 * 1024 + tid * 4];
            xq1 = *(const float4*)&xb[1 * 1024 + tid * 4];
            xq2 = *(const float4*)&xb[2 * 1024 + tid * 4];
            xq3 = *(const float4*)&xb[3 * 1024 + tid * 4];
        }

        {
            u64 accB0 = 0, accB1 = 0;
            const int kbase = ks * 256;
#pragma unroll 4
            for (int k = 0; k < 256; k++) {
                float a = sH[(kbase + k) * 16 + bl];
                ulonglong2 wv = *(const ulonglong2*)&sWhr[(kbase + k) * 16 + pq * 4];
                u64 ap = pack2(a, a);
                accB0 = ffma2(ap, wv.x, accB0);
                accB1 = ffma2(ap, wv.y, accB1);
            }
            float4 r4;
            unpack2(accB0, r4.x, r4.y);
            unpack2(accB1, r4.z, r4.w);
            *(float4*)&sPre[ks * 256 + rr * 4] = r4;
        }
        __syncthreads();
        if (tid < 64) {
            float4 v0 = *(const float4*)&sPre[      tid * 4];
            float4 v1 = *(const float4*)&sPre[256 + tid * 4];
            float4 v2 = *(const float4*)&sPre[512 + tid * 4];
            float4 v3 = *(const float4*)&sPre[768 + tid * 4];
            float4 v;
            v.x = v0.x + v1.x + v2.x + v3.x;
            v.y = v0.y + v1.y + v2.y + v3.y;
            v.z = v0.z + v1.z + v2.z + v3.z;
            v.w = v0.w + v1.w + v2.w + v3.w;
            int b = bB0 + (tid & 15);
            int p = p0 + (tid >> 4) * 4;
            hT[(p + 0) * 64 + b] = v.x;
            hT[(p + 1) * 64 + b] = v.y;
            hT[(p + 2) * 64 + b] = v.z;
            hT[(p + 3) * 64 + b] = v.w;
            *(float4*)&out[((size_t)b * SS + tpos) * 512 + d * PP + p] = v;
        }
        gsync_dir(d, grp, ++tgt);
    }
}

// ---------------- launch ----------------
extern "C" void kernel_launch(void* const* d_in, const int* in_sizes, int n_in,
                              void* d_out, int out_size) {
    (void)in_sizes; (void)n_in; (void)out_size;
    const float* x     = (const float*)d_in[0];
    const float* WihF  = (const float*)d_in[1];
    const float* WhhF  = (const float*)d_in[2];
    const float* bihF  = (const float*)d_in[3];
    const float* bhhF  = (const float*)d_in[4];
    const float* WhrF  = (const float*)d_in[5];
    const float* WihB  = (const float*)d_in[6];
    const float* WhhB  = (const float*)d_in[7];
    const float* bihB  = (const float*)d_in[8];
    const float* bhhB  = (const float*)d_in[9];
    const float* WhrB  = (const float*)d_in[10];
    float* out = (float*)d_out;

    // Non-stream API: executes immediately (first call happens in the
    // uncaptured correctness invocation), idempotent thereafter.
    cudaFuncSetAttribute(lstm_recur2,
                         cudaFuncAttributeMaxDynamicSharedMemorySize,
                         SM_TOTF * (int)sizeof(float));

    prep_kernel<<<2048, 256>>>(x, WihF, WhhF, bihF, bhhF, WhrF,
                                  WihB, WhhB, bihB, bhhB, WhrB);
    dim3 g(1024, 64, 2);     // (t, n/64, dir)
    xg_gemm_kernel<<<g, 256>>>();
    lstm_recur2<<<NCTA, 256, SM_TOTF * (int)sizeof(float)>>>(out);
}